// round 8
// baseline (speedup 1.0000x reference)
#include <cuda_runtime.h>

// Gray-Scott reaction-diffusion residual.
// y-march + float2 in z + x-PAIR per thread (8 outputs/thread/iter).
// v8 = v7 with the block-residency cap raised from 5 to 7 blocks/SM.
// Input:  output [50, 2, 100, 100, 100] fp32  (d_in[0])
// Output: f_u (48,96,96,96) then f_v (48,96,96,96), fp32.

#define SLICE_C  1000000      // u->v channel offset (floats)
#define STRIDE_T 2000000      // per-timestep offset (floats)
#define PLANE    10000
#define ROW      100
#define OUTE     96
#define OUTP     (96*96)
#define OUTVOL   (96*96*96)
#define YCHUNK   24

#define LD2(p, off) (*(const float2*)((p) + (off)))

__device__ __forceinline__ float2 lap2(
    float2 c, float2 zl, float2 zr,
    float2 x1a, float2 x1b, float2 x2a, float2 x2b,
    float2 y1a, float2 y1b, float2 y2a, float2 y2b)
{
    const float S0 = -1.0f / 12.0f;
    const float S1 = 4.0f / 3.0f;
    const float SC = -7.5f;
    const float DXv = 100.0f / 48.0f;
    const float INV_DX2 = 1.0f / (DXv * DXv);
    float s1x = zl.y + c.y + x1a.x + x1b.x + y1a.x + y1b.x;
    float s2x = zl.x + zr.x + x2a.x + x2b.x + y2a.x + y2b.x;
    float s1y = c.x + zr.x + x1a.y + x1b.y + y1a.y + y1b.y;
    float s2y = zl.y + zr.y + x2a.y + x2b.y + y2a.y + y2b.y;
    float2 r;
    r.x = (S1 * s1x + S0 * s2x + SC * c.x) * INV_DX2;
    r.y = (S1 * s1y + S0 * s2y + SC * c.y) * INV_DX2;
    return r;
}

__global__ void __launch_bounds__(96, 7) gs_residual_v8(
    const float* __restrict__ in, float* __restrict__ out)
{
    const int zp = threadIdx.x;                    // 0..47 (z pair)
    const int z  = zp * 2;
    const int x  = blockIdx.x * 4 + threadIdx.y * 2;   // thread handles rows x, x+1
    const int yb = blockIdx.y * YCHUNK;
    const int t  = blockIdx.z;

    // p -> center f2 of input row (x+2), plane yb, channel u, time t.
    const float* p  = in + (long long)t * STRIDE_T
                         + (long long)yb * PLANE
                         + (x + 2) * ROW + (z + 2);
    const float* pn = p + STRIDE_T;                // t+1 (center-plane reads only)

    const float INV_DT = 2.0f;
    const float DU = 0.2f, DV = 0.1f, FF = 0.025f, KK = 0.055f;

    // y-queue of centers for the two rows: [plane][row 0/1]
    float2 qu[5][2], qv[5][2];
#pragma unroll
    for (int i = 0; i < 4; i++) {
        qu[i][0] = LD2(p, i * PLANE);
        qu[i][1] = LD2(p, i * PLANE + ROW);
        qv[i][0] = LD2(p, i * PLANE + SLICE_C);
        qv[i][1] = LD2(p, i * PLANE + ROW + SLICE_C);
    }

    float* ou = out + t * OUTVOL + yb * OUTP + x * OUTE + z;
    float* ov = ou + 48 * OUTVOL;

#pragma unroll 1
    for (int yy = 0; yy < YCHUNK; yy++) {
        // ---- channel u loads (12 f2) ----
        float2 qu40 = LD2(p, 4 * PLANE);
        float2 qu41 = LD2(p, 4 * PLANE + ROW);
        float2 uzl0 = LD2(p, 2 * PLANE - 2);
        float2 uzr0 = LD2(p, 2 * PLANE + 2);
        float2 uzl1 = LD2(p, 2 * PLANE + ROW - 2);
        float2 uzr1 = LD2(p, 2 * PLANE + ROW + 2);
        float2 uxa  = LD2(p, 2 * PLANE - 2 * ROW);   // row x
        float2 uxb  = LD2(p, 2 * PLANE - ROW);       // row x+1
        float2 uxc  = LD2(p, 2 * PLANE + 2 * ROW);   // row x+4
        float2 uxd  = LD2(p, 2 * PLANE + 3 * ROW);   // row x+5
        float2 un0  = LD2(pn, 2 * PLANE);
        float2 un1  = LD2(pn, 2 * PLANE + ROW);
        // ---- channel v loads (12 f2) ----
        float2 qv40 = LD2(p, 4 * PLANE + SLICE_C);
        float2 qv41 = LD2(p, 4 * PLANE + ROW + SLICE_C);
        float2 vzl0 = LD2(p, 2 * PLANE - 2 + SLICE_C);
        float2 vzr0 = LD2(p, 2 * PLANE + 2 + SLICE_C);
        float2 vzl1 = LD2(p, 2 * PLANE + ROW - 2 + SLICE_C);
        float2 vzr1 = LD2(p, 2 * PLANE + ROW + 2 + SLICE_C);
        float2 vxa  = LD2(p, 2 * PLANE - 2 * ROW + SLICE_C);
        float2 vxb  = LD2(p, 2 * PLANE - ROW + SLICE_C);
        float2 vxc  = LD2(p, 2 * PLANE + 2 * ROW + SLICE_C);
        float2 vxd  = LD2(p, 2 * PLANE + 3 * ROW + SLICE_C);
        float2 vn0  = LD2(pn, 2 * PLANE + SLICE_C);
        float2 vn1  = LD2(pn, 2 * PLANE + ROW + SLICE_C);

        qu[4][0] = qu40; qu[4][1] = qu41;
        qv[4][0] = qv40; qv[4][1] = qv41;

        // ---- laplacians ----
        // output row x:   x-taps ±1 -> rows x+1 (uxb), x+3 (qu[2][1]); ±2 -> rows x (uxa), x+4 (uxc)
        float2 lapu0 = lap2(qu[2][0], uzl0, uzr0, uxb, qu[2][1], uxa, uxc,
                            qu[1][0], qu[3][0], qu[0][0], qu[4][0]);
        float2 lapv0 = lap2(qv[2][0], vzl0, vzr0, vxb, qv[2][1], vxa, vxc,
                            qv[1][0], qv[3][0], qv[0][0], qv[4][0]);
        // output row x+1: x-taps ±1 -> rows x+2 (qu[2][0]), x+4 (uxc); ±2 -> rows x+1 (uxb), x+5 (uxd)
        float2 lapu1 = lap2(qu[2][1], uzl1, uzr1, qu[2][0], uxc, uxb, uxd,
                            qu[1][1], qu[3][1], qu[0][1], qu[4][1]);
        float2 lapv1 = lap2(qv[2][1], vzl1, vzr1, qv[2][0], vxc, vxb, vxd,
                            qv[1][1], qv[3][1], qv[0][1], qv[4][1]);

        // ---- reaction + time derivative, row x ----
        {
            float2 uc = qu[2][0], vc = qv[2][0];
            float uvv0 = uc.x * vc.x * vc.x;
            float uvv1 = uc.y * vc.y * vc.y;
            float2 fu, fv;
            fu.x = DU * lapu0.x - uvv0 + FF * (1.0f - uc.x) - (un0.x - uc.x) * INV_DT;
            fu.y = DU * lapu0.y - uvv1 + FF * (1.0f - uc.y) - (un0.y - uc.y) * INV_DT;
            fv.x = DV * lapv0.x + uvv0 - (FF + KK) * vc.x - (vn0.x - vc.x) * INV_DT;
            fv.y = DV * lapv0.y + uvv1 - (FF + KK) * vc.y - (vn0.y - vc.y) * INV_DT;
            *(float2*)ou = fu;
            *(float2*)ov = fv;
        }
        // ---- reaction + time derivative, row x+1 ----
        {
            float2 uc = qu[2][1], vc = qv[2][1];
            float uvv0 = uc.x * vc.x * vc.x;
            float uvv1 = uc.y * vc.y * vc.y;
            float2 fu, fv;
            fu.x = DU * lapu1.x - uvv0 + FF * (1.0f - uc.x) - (un1.x - uc.x) * INV_DT;
            fu.y = DU * lapu1.y - uvv1 + FF * (1.0f - uc.y) - (un1.y - uc.y) * INV_DT;
            fv.x = DV * lapv1.x + uvv0 - (FF + KK) * vc.x - (vn1.x - vc.x) * INV_DT;
            fv.y = DV * lapv1.y + uvv1 - (FF + KK) * vc.y - (vn1.y - vc.y) * INV_DT;
            *(float2*)(ou + OUTE) = fu;
            *(float2*)(ov + OUTE) = fv;
        }

        ou += OUTP;
        ov += OUTP;
        p  += PLANE;
        pn += PLANE;

        // shift queues
#pragma unroll
        for (int i = 0; i < 4; i++) {
            qu[i][0] = qu[i + 1][0]; qu[i][1] = qu[i + 1][1];
            qv[i][0] = qv[i + 1][0]; qv[i][1] = qv[i + 1][1];
        }
    }
}

extern "C" void kernel_launch(void* const* d_in, const int* in_sizes, int n_in,
                              void* d_out, int out_size)
{
    const float* in = (const float*)d_in[0];
    float* out = (float*)d_out;
    dim3 grid(24, 4, 48);    // x-tiles (4 x-rows each), y-chunks, t
    dim3 block(48, 2);       // z-pairs, x-pairs
    gs_residual_v8<<<grid, block>>>(in, out);
}

// round 9
// speedup vs baseline: 1.0609x; 1.0609x over previous
#include <cuda_runtime.h>

// Gray-Scott reaction-diffusion residual, v9 = v4 + z-halo via warp shuffle.
// y-march (chunked) + float2 in z; z-halo comes from neighbor lanes' center
// registers (shfl), with predicated loads only at warp/row seams.
// Input:  output [50, 2, 100, 100, 100] fp32  (d_in[0])
// Output: f_u (48,96,96,96) then f_v (48,96,96,96), fp32.

#define SLICE_C  1000000      // 100^3
#define STRIDE_T 2000000      // 2 channels
#define PLANE    10000        // 100*100
#define ROW      100
#define OUTE     96
#define OUTP     (96*96)      // 9216
#define OUTVOL   (96*96*96)   // 884736
#define YCHUNK   24           // y steps per block (96/4)

__global__ void __launch_bounds__(192) gs_residual_v9(
    const float* __restrict__ in, float* __restrict__ out)
{
    const int zp = threadIdx.x;                    // 0..47 (z pair)
    const int z  = zp * 2;                         // output z (even)
    const int x  = blockIdx.x * 4 + threadIdx.y;   // 0..95
    const int yb = blockIdx.y * YCHUNK;            // output y chunk start
    const int t  = blockIdx.z;                     // 0..47

    const int lin  = threadIdx.x + 48 * threadIdx.y;
    const int lane = lin & 31;
    const bool edgeL = (threadIdx.x == 0)  || (lane == 0);
    const bool edgeR = (threadIdx.x == 47) || (lane == 31);

    const float* __restrict__ u = in + (long long)t * STRIDE_T;
    const float* __restrict__ v = u + SLICE_C;
    const float* __restrict__ un_p = u + STRIDE_T;   // t+1, channel u
    const float* __restrict__ vn_p = v + STRIDE_T;   // t+1, channel v

    // offset of the center float2 within an input y-plane (covers input z+2, z+3)
    const int base = (x + 2) * ROW + (z + 2);

    const float S0 = -1.0f / 12.0f;
    const float S1 = 4.0f / 3.0f;
    const float SC = -7.5f;
    const float DXv = 100.0f / 48.0f;
    const float INV_DX2 = 1.0f / (DXv * DXv);
    const float INV_DT = 2.0f;               // 1/0.5
    const float DU = 0.2f, DV = 0.1f, FF = 0.025f, KK = 0.055f;

    // register queue of center float2s for input planes yb .. yb+3
    float2 qu[5], qv[5];
#pragma unroll
    for (int i = 0; i < 4; i++) {
        qu[i] = *(const float2*)(u + (yb + i) * PLANE + base);
        qv[i] = *(const float2*)(v + (yb + i) * PLANE + base);
    }

    int oidx = t * OUTVOL + yb * OUTP + x * OUTE + z;   // output index for yc=yb

#pragma unroll 2
    for (int yy = 0; yy < YCHUNK; yy++) {
        const int yc = yb + yy;
        const int pc = (yc + 2) * PLANE + base;   // center plane index

        // new far-plane centers (y+4)
        qu[4] = *(const float2*)(u + (yc + 4) * PLANE + base);
        qv[4] = *(const float2*)(v + (yc + 4) * PLANE + base);

        float2 uc = qu[2];
        float2 vc = qv[2];

        // z-halo via shuffle: lane zp-1 holds centers (z, z+1) = uzl;
        //                     lane zp+1 holds centers (z+4, z+5) = uzr.
        float2 uzl, uzr, vzl, vzr;
        uzl.x = __shfl_up_sync(0xffffffffu, uc.x, 1);
        uzl.y = __shfl_up_sync(0xffffffffu, uc.y, 1);
        vzl.x = __shfl_up_sync(0xffffffffu, vc.x, 1);
        vzl.y = __shfl_up_sync(0xffffffffu, vc.y, 1);
        uzr.x = __shfl_down_sync(0xffffffffu, uc.x, 1);
        uzr.y = __shfl_down_sync(0xffffffffu, uc.y, 1);
        vzr.x = __shfl_down_sync(0xffffffffu, vc.x, 1);
        vzr.y = __shfl_down_sync(0xffffffffu, vc.y, 1);
        if (edgeL) {
            uzl = *(const float2*)(u + pc - 2);
            vzl = *(const float2*)(v + pc - 2);
        }
        if (edgeR) {
            uzr = *(const float2*)(u + pc + 2);
            vzr = *(const float2*)(v + pc + 2);
        }

        // x taps
        float2 uxm1 = *(const float2*)(u + pc - ROW);
        float2 uxp1 = *(const float2*)(u + pc + ROW);
        float2 uxm2 = *(const float2*)(u + pc - 2 * ROW);
        float2 uxp2 = *(const float2*)(u + pc + 2 * ROW);
        float2 vxm1 = *(const float2*)(v + pc - ROW);
        float2 vxp1 = *(const float2*)(v + pc + ROW);
        float2 vxm2 = *(const float2*)(v + pc - 2 * ROW);
        float2 vxp2 = *(const float2*)(v + pc + 2 * ROW);

        // t+1 centers
        float2 unx = *(const float2*)(un_p + pc);
        float2 vnx = *(const float2*)(vn_p + pc);

        // ---- u laplacian ----
        // point 0 (input z+2): z±1 = uzl.y, uc.y ; z±2 = uzl.x, uzr.x
        float s1u0 = uzl.y + uc.y + uxm1.x + uxp1.x + qu[1].x + qu[3].x;
        float s2u0 = uzl.x + uzr.x + uxm2.x + uxp2.x + qu[0].x + qu[4].x;
        // point 1 (input z+3): z±1 = uc.x, uzr.x ; z±2 = uzl.y, uzr.y
        float s1u1 = uc.x + uzr.x + uxm1.y + uxp1.y + qu[1].y + qu[3].y;
        float s2u1 = uzl.y + uzr.y + uxm2.y + uxp2.y + qu[0].y + qu[4].y;
        float lapu0 = (S1 * s1u0 + S0 * s2u0 + SC * uc.x) * INV_DX2;
        float lapu1 = (S1 * s1u1 + S0 * s2u1 + SC * uc.y) * INV_DX2;

        // ---- v laplacian ----
        float s1v0 = vzl.y + vc.y + vxm1.x + vxp1.x + qv[1].x + qv[3].x;
        float s2v0 = vzl.x + vzr.x + vxm2.x + vxp2.x + qv[0].x + qv[4].x;
        float s1v1 = vc.x + vzr.x + vxm1.y + vxp1.y + qv[1].y + qv[3].y;
        float s2v1 = vzl.y + vzr.y + vxm2.y + vxp2.y + qv[0].y + qv[4].y;
        float lapv0 = (S1 * s1v0 + S0 * s2v0 + SC * vc.x) * INV_DX2;
        float lapv1 = (S1 * s1v1 + S0 * s2v1 + SC * vc.y) * INV_DX2;

        // ---- reaction + time derivative ----
        float uvv0 = uc.x * vc.x * vc.x;
        float uvv1 = uc.y * vc.y * vc.y;
        float ut0 = (unx.x - uc.x) * INV_DT;
        float ut1 = (unx.y - uc.y) * INV_DT;
        float vt0 = (vnx.x - vc.x) * INV_DT;
        float vt1 = (vnx.y - vc.y) * INV_DT;

        float2 fu, fv;
        fu.x = DU * lapu0 - uvv0 + FF * (1.0f - uc.x) - ut0;
        fu.y = DU * lapu1 - uvv1 + FF * (1.0f - uc.y) - ut1;
        fv.x = DV * lapv0 + uvv0 - (FF + KK) * vc.x - vt0;
        fv.y = DV * lapv1 + uvv1 - (FF + KK) * vc.y - vt1;

        *(float2*)(out + oidx) = fu;
        *(float2*)(out + 48 * OUTVOL + oidx) = fv;
        oidx += OUTP;

        // shift queues
        qu[0] = qu[1]; qu[1] = qu[2]; qu[2] = qu[3]; qu[3] = qu[4];
        qv[0] = qv[1]; qv[1] = qv[2]; qv[2] = qv[3]; qv[3] = qv[4];
    }
}

extern "C" void kernel_launch(void* const* d_in, const int* in_sizes, int n_in,
                              void* d_out, int out_size)
{
    const float* in = (const float*)d_in[0];
    float* out = (float*)d_out;
    dim3 grid(24, 4, 48);    // x-tiles (96/4), y-chunks, t
    dim3 block(48, 4);       // z-pairs, x within tile
    gs_residual_v9<<<grid, block>>>(in, out);
}